// round 10
// baseline (speedup 1.0000x reference)
#include <cuda_runtime.h>
#include <cuda_bf16.h>
#include <cstdint>

// MotionLoss: per-row small-angle HTM chain + global MSE reduction.
// inputs  : [512,1024,18] f32   (d_in[0])
// targets : [512,1024, 7] f32   (d_in[1])
// out     : scalar f32
//
// TMA 4-stage pipeline + L2 evict_last. Issue-at-top (R9) with the off-by-one
// fixed: at iteration it we arm slot (it+3)%4 (tile bid+(it+3)*NBLK) BEFORE
// waiting on slot it%4 — including it=0, whose armed slot 3 the prologue
// deliberately left empty. R9's `it>0` guard skipped tile bid+3*NBLK -> hang.

#define TPB 256
#define ROWS_TILE 256
#define NSTAGE 4
#define NBLK 296                       // 2 CTAs/SM * 148 SMs

#define TILE_IN_FLOATS (ROWS_TILE * 18)        // 4608
#define TILE_TG_FLOATS (ROWS_TILE * 7)         // 1792
#define TILE_FLOATS    (ROWS_TILE * 25)        // 6400
#define TILE_IN_BYTES  (TILE_IN_FLOATS * 4)    // 18432
#define TILE_TG_BYTES  (TILE_TG_FLOATS * 4)    // 7168
#define TILE_BYTES     (TILE_FLOATS * 4)       // 25600

__device__ float g_partials[NBLK];
__device__ unsigned int g_ticket = 0;

__device__ __forceinline__ uint32_t smem_u32(const void* p) {
    return (uint32_t)__cvta_generic_to_shared(p);
}
__device__ __forceinline__ void mbar_init(uint32_t addr, uint32_t count) {
    asm volatile("mbarrier.init.shared.b64 [%0], %1;" :: "r"(addr), "r"(count) : "memory");
}
__device__ __forceinline__ void mbar_expect_tx(uint32_t addr, uint32_t bytes) {
    asm volatile("mbarrier.arrive.expect_tx.shared.b64 _, [%0], %1;"
                 :: "r"(addr), "r"(bytes) : "memory");
}
__device__ __forceinline__ uint64_t make_evict_last_policy() {
    uint64_t pol;
    asm volatile("createpolicy.fractional.L2::evict_last.b64 %0, 1.0;" : "=l"(pol));
    return pol;
}
__device__ __forceinline__ void bulk_g2s_hint(uint32_t dst, const void* src,
                                              uint32_t bytes, uint32_t mbar,
                                              uint64_t pol) {
    asm volatile(
        "cp.async.bulk.shared::cluster.global.mbarrier::complete_tx::bytes.L2::cache_hint "
        "[%0], [%1], %2, [%3], %4;"
        :: "r"(dst), "l"(src), "r"(bytes), "r"(mbar), "l"(pol) : "memory");
}
__device__ __forceinline__ void mbar_wait(uint32_t addr, uint32_t parity) {
    uint32_t done;
    asm volatile(
        "{\n\t.reg .pred p;\n\t"
        "mbarrier.try_wait.parity.acquire.cta.shared::cta.b64 p, [%1], %2;\n\t"
        "selp.b32 %0, 1, 0, p;\n\t}"
        : "=r"(done) : "r"(addr), "r"(parity) : "memory");
    if (!done) {
        asm volatile(
            "{\n\t.reg .pred P1;\n\t"
            "WAIT_LOOP_%=:\n\t"
            "mbarrier.try_wait.parity.acquire.cta.shared::cta.b64 P1, [%0], %1, 0x989680;\n\t"
            "@P1 bra.uni WAIT_DONE_%=;\n\t"
            "bra.uni WAIT_LOOP_%=;\n\t"
            "WAIT_DONE_%=:\n\t}"
            :: "r"(addr), "r"(parity) : "memory");
    }
}

__global__ __launch_bounds__(TPB) void motion_loss_tma_l2c(
    const float* __restrict__ in, const float* __restrict__ tgt,
    float* __restrict__ out, int n_rows)
{
    extern __shared__ float smem[];                 // [NSTAGE*TILE_FLOATS] + barriers
    uint64_t* mbar = (uint64_t*)(smem + NSTAGE * TILE_FLOATS);

    const int T = n_rows / ROWS_TILE;               // 2048 full tiles
    const int bid = blockIdx.x;
    const int tid = threadIdx.x;

    if (tid == 0) {
        #pragma unroll
        for (int s = 0; s < NSTAGE; ++s) mbar_init(smem_u32(&mbar[s]), 1);
    }
    asm volatile("fence.proxy.async.shared::cta;" ::: "memory");
    __syncthreads();

    const uint64_t pol = make_evict_last_policy();

    auto issue_tile = [&](int tile, int slot) {     // tid==0 only
        uint32_t bar = smem_u32(&mbar[slot]);
        uint32_t dst = smem_u32(smem + slot * TILE_FLOATS);
        mbar_expect_tx(bar, TILE_BYTES);
        bulk_g2s_hint(dst, in + (size_t)tile * TILE_IN_FLOATS,
                      TILE_IN_BYTES, bar, pol);
        bulk_g2s_hint(dst + TILE_IN_BYTES, tgt + (size_t)tile * TILE_TG_FLOATS,
                      TILE_TG_BYTES, bar, pol);
    };

    // ---- prologue: fill slots 0..NSTAGE-2 (slot NSTAGE-1 armed at it=0) ----
    if (tid == 0) {
        for (int it = 0; it < NSTAGE - 1; ++it) {
            int tile = bid + it * NBLK;
            if (tile < T) issue_tile(tile, it);
        }
    }

    // ---- main loop ----
    float acc = 0.0f;
    int it = 0;
    for (int tile = bid; tile < T; tile += NBLK, ++it) {
        // Issue-at-top: arm slot (it+NSTAGE-1)%NSTAGE for tile it+NSTAGE-1.
        // it=0: that slot (3) is empty from the prologue. it>=1: that slot
        // ((it-1)%NSTAGE) was drained at the syncthreads ending iteration it-1.
        if (tid == 0) {
            int nxt_it = it + NSTAGE - 1;
            int nxt_tile = bid + nxt_it * NBLK;
            if (nxt_tile < T) issue_tile(nxt_tile, nxt_it % NSTAGE);
        }

        const int slot = it % NSTAGE;
        const uint32_t parity = (uint32_t)((it / NSTAGE) & 1);
        mbar_wait(smem_u32(&mbar[slot]), parity);

        const float* vp = &smem[slot * TILE_FLOATS + tid * 18];
        const float* t  = &smem[slot * TILE_FLOATS + TILE_IN_FLOATS + tid * 7];

        // float2 reads: 9 LDS.64 (72B row stride, 8B aligned)
        const float2* v2 = (const float2*)vp;
        float2 q0 = v2[0], q1 = v2[1], q2 = v2[2], q3 = v2[3], q4 = v2[4];
        float2 q5 = v2[5], q6 = v2[6], q7 = v2[7], q8 = v2[8];
        const float p0 = q0.x, p1 = q0.y, p2 = q1.x;
        const float s00 = q1.y, s01 = q2.x;
        const float s10 = q2.y, s11 = q3.x;
        const float s20 = q3.y, s21 = q4.x;
        const float exX = q4.y, eyX = q5.x, ezX = q5.y;
        const float exY = q6.x, eyY = q6.y, ezY = q7.x;
        const float exZ = q7.y, eyZ = q8.x, ezZ = q8.y;

        const float x = t[4], y = t[5], z = t[6];

        // w = MX * (MY * (MZ * P)), P=(x,y,z,1)
        float ax = x - ezZ * y + eyZ * z + s20;
        float ay = ezZ * x + y - exZ * z + s21;
        float az = -eyZ * x + exZ * y + z + p2;
        float bx = ax - ezY * ay + eyY * az + s10;
        float by = ezY * ax + ay - exY * az + p1;
        float bz = -eyY * ax + exY * ay + az + s11;
        float cx = bx - ezX * by + eyX * bz + p0;
        float cy = ezX * bx + by - exX * bz + s00;
        float cz = -eyX * bx + exX * by + bz + s01;

        const float m1 = cx - x;
        const float m2 = cy - y;
        const float m3 = cz - z;
        const float err = sqrtf(m1 * m1 + m2 * m2 + m3 * m3 + 1e-12f);

        const float d0 = err - t[0];
        const float d1 = m1 - t[1];
        const float d2 = m2 - t[2];
        const float d3 = m3 - t[3];
        acc += d0 * d0 + d1 * d1 + d2 * d2 + d3 * d3;

        __syncthreads();            // all readers done before slot reuse
    }

    // ---- block reduction (deterministic) ----
    #pragma unroll
    for (int off = 16; off > 0; off >>= 1)
        acc += __shfl_down_sync(0xFFFFFFFFu, acc, off);

    __shared__ float s_warp[TPB / 32];
    const int lane = tid & 31;
    const int wid  = tid >> 5;
    if (lane == 0) s_warp[wid] = acc;
    __syncthreads();
    if (wid == 0) {
        float a = (lane < TPB / 32) ? s_warp[lane] : 0.0f;
        #pragma unroll
        for (int off = 4; off > 0; off >>= 1)
            a += __shfl_down_sync(0xFFFFFFFFu, a, off);
        if (lane == 0) g_partials[bid] = a;
    }

    // ---- last-block-done final reduce ----
    __shared__ bool s_last;
    __threadfence();
    if (tid == 0) {
        unsigned int tk = atomicAdd(&g_ticket, 1u);
        s_last = (tk == gridDim.x - 1);
    }
    __syncthreads();
    if (!s_last) return;

    double sum = 0.0;
    for (int i = tid; i < (int)gridDim.x; i += TPB)
        sum += (double)__ldcg(&g_partials[i]);

    if (tid == 0) {   // remainder rows (none for 512*1024; safety)
        for (int r = T * ROWS_TILE; r < n_rows; ++r) {
            const float* v = in + (size_t)r * 18;
            const float* t = tgt + (size_t)r * 7;
            float x = t[4], y = t[5], z = t[6];
            float ax = x - v[17]*y + v[16]*z + v[7];
            float ay = v[17]*x + y - v[15]*z + v[8];
            float az = -v[16]*x + v[15]*y + z + v[2];
            float bx = ax - v[14]*ay + v[13]*az + v[5];
            float by = v[14]*ax + ay - v[12]*az + v[1];
            float bz = -v[13]*ax + v[12]*ay + az + v[6];
            float cx = bx - v[11]*by + v[10]*bz + v[0];
            float cy = v[11]*bx + by - v[9]*bz + v[3];
            float cz = -v[10]*bx + v[9]*by + bz + v[4];
            float m1 = cx - x, m2 = cy - y, m3 = cz - z;
            float err = sqrtf(m1*m1 + m2*m2 + m3*m3 + 1e-12f);
            float d0 = err - t[0], d1 = m1 - t[1], d2 = m2 - t[2], d3 = m3 - t[3];
            sum += (double)(d0*d0 + d1*d1 + d2*d2 + d3*d3);
        }
    }

    __shared__ double s_fin[TPB];
    s_fin[tid] = sum;
    __syncthreads();
    #pragma unroll
    for (int off = TPB / 2; off > 0; off >>= 1) {
        if (tid < off) s_fin[tid] += s_fin[tid + off];
        __syncthreads();
    }
    if (tid == 0) {
        out[0] = (float)(s_fin[0] / ((double)n_rows * 4.0));
        g_ticket = 0;   // reset for next graph replay
    }
}

extern "C" void kernel_launch(void* const* d_in, const int* in_sizes, int n_in,
                              void* d_out, int out_size)
{
    const float* inputs  = (const float*)d_in[0];
    const float* targets = (const float*)d_in[1];
    float* out = (float*)d_out;

    const int n_rows = in_sizes[0] / 18;                       // 524288
    const int smem_bytes = NSTAGE * TILE_BYTES + NSTAGE * 8;   // 102432

    static bool attr_set = false;
    if (!attr_set) {
        cudaFuncSetAttribute(motion_loss_tma_l2c,
                             cudaFuncAttributeMaxDynamicSharedMemorySize,
                             smem_bytes);
        attr_set = true;
    }

    motion_loss_tma_l2c<<<NBLK, TPB, smem_bytes>>>(inputs, targets, out, n_rows);
}

// round 13
// speedup vs baseline: 1.1063x; 1.1063x over previous
#include <cuda_runtime.h>
#include <cuda_bf16.h>
#include <cstdint>

// MotionLoss: per-row small-angle HTM chain + global MSE reduction.
// inputs  : [512,1024,18] f32   (d_in[0])
// targets : [512,1024, 7] f32   (d_in[1])
// out     : scalar f32
//
// R8 skeleton (TMA 4-stage, bottom-issue, evict_last) with 128-row tiles and
// 4 CTAs/SM: same in-flight bytes per SM, 2x independent TMA streams, half
// the serial work quantum per pipeline step.

#define TPB 128
#define ROWS_TILE 128
#define NSTAGE 4
#define NBLK 592                       // 4 CTAs/SM * 148 SMs

#define TILE_IN_FLOATS (ROWS_TILE * 18)        // 2304
#define TILE_TG_FLOATS (ROWS_TILE * 7)         // 896
#define TILE_FLOATS    (ROWS_TILE * 25)        // 3200
#define TILE_IN_BYTES  (TILE_IN_FLOATS * 4)    // 9216
#define TILE_TG_BYTES  (TILE_TG_FLOATS * 4)    // 3584
#define TILE_BYTES     (TILE_FLOATS * 4)       // 12800

__device__ float g_partials[NBLK];
__device__ unsigned int g_ticket = 0;

__device__ __forceinline__ uint32_t smem_u32(const void* p) {
    return (uint32_t)__cvta_generic_to_shared(p);
}
__device__ __forceinline__ void mbar_init(uint32_t addr, uint32_t count) {
    asm volatile("mbarrier.init.shared.b64 [%0], %1;" :: "r"(addr), "r"(count) : "memory");
}
__device__ __forceinline__ void mbar_expect_tx(uint32_t addr, uint32_t bytes) {
    asm volatile("mbarrier.arrive.expect_tx.shared.b64 _, [%0], %1;"
                 :: "r"(addr), "r"(bytes) : "memory");
}
__device__ __forceinline__ uint64_t make_evict_last_policy() {
    uint64_t pol;
    asm volatile("createpolicy.fractional.L2::evict_last.b64 %0, 1.0;" : "=l"(pol));
    return pol;
}
__device__ __forceinline__ void bulk_g2s_hint(uint32_t dst, const void* src,
                                              uint32_t bytes, uint32_t mbar,
                                              uint64_t pol) {
    asm volatile(
        "cp.async.bulk.shared::cluster.global.mbarrier::complete_tx::bytes.L2::cache_hint "
        "[%0], [%1], %2, [%3], %4;"
        :: "r"(dst), "l"(src), "r"(bytes), "r"(mbar), "l"(pol) : "memory");
}
__device__ __forceinline__ void mbar_wait(uint32_t addr, uint32_t parity) {
    uint32_t done;
    asm volatile(
        "{\n\t.reg .pred p;\n\t"
        "mbarrier.try_wait.parity.acquire.cta.shared::cta.b64 p, [%1], %2;\n\t"
        "selp.b32 %0, 1, 0, p;\n\t}"
        : "=r"(done) : "r"(addr), "r"(parity) : "memory");
    if (!done) {
        asm volatile(
            "{\n\t.reg .pred P1;\n\t"
            "WAIT_LOOP_%=:\n\t"
            "mbarrier.try_wait.parity.acquire.cta.shared::cta.b64 P1, [%0], %1, 0x989680;\n\t"
            "@P1 bra.uni WAIT_DONE_%=;\n\t"
            "bra.uni WAIT_LOOP_%=;\n\t"
            "WAIT_DONE_%=:\n\t}"
            :: "r"(addr), "r"(parity) : "memory");
    }
}

__global__ __launch_bounds__(TPB) void motion_loss_tma4(
    const float* __restrict__ in, const float* __restrict__ tgt,
    float* __restrict__ out, int n_rows)
{
    extern __shared__ float smem[];                 // [NSTAGE*TILE_FLOATS] + barriers
    uint64_t* mbar = (uint64_t*)(smem + NSTAGE * TILE_FLOATS);

    const int T = n_rows / ROWS_TILE;               // 4096 full tiles
    const int bid = blockIdx.x;
    const int tid = threadIdx.x;

    if (tid == 0) {
        #pragma unroll
        for (int s = 0; s < NSTAGE; ++s) mbar_init(smem_u32(&mbar[s]), 1);
    }
    asm volatile("fence.proxy.async.shared::cta;" ::: "memory");
    __syncthreads();

    const uint64_t pol = make_evict_last_policy();

    auto issue_tile = [&](int tile, int slot) {     // tid==0 only
        uint32_t bar = smem_u32(&mbar[slot]);
        uint32_t dst = smem_u32(smem + slot * TILE_FLOATS);
        mbar_expect_tx(bar, TILE_BYTES);
        bulk_g2s_hint(dst, in + (size_t)tile * TILE_IN_FLOATS,
                      TILE_IN_BYTES, bar, pol);
        bulk_g2s_hint(dst + TILE_IN_BYTES, tgt + (size_t)tile * TILE_TG_FLOATS,
                      TILE_TG_BYTES, bar, pol);
    };

    // ---- prologue: fill NSTAGE-1 stages ----
    if (tid == 0) {
        for (int it = 0; it < NSTAGE - 1; ++it) {
            int tile = bid + it * NBLK;
            if (tile < T) issue_tile(tile, it);
        }
    }

    // ---- main loop (bottom-issue, as in R8) ----
    float acc = 0.0f;
    int it = 0;
    for (int tile = bid; tile < T; tile += NBLK, ++it) {
        const int slot = it % NSTAGE;
        const uint32_t parity = (uint32_t)((it / NSTAGE) & 1);
        mbar_wait(smem_u32(&mbar[slot]), parity);

        const float* vp = &smem[slot * TILE_FLOATS + tid * 18];
        const float* t  = &smem[slot * TILE_FLOATS + TILE_IN_FLOATS + tid * 7];

        // float2 reads: 9 LDS.64 (72B row stride, 8B aligned)
        const float2* v2 = (const float2*)vp;
        float2 q0 = v2[0], q1 = v2[1], q2 = v2[2], q3 = v2[3], q4 = v2[4];
        float2 q5 = v2[5], q6 = v2[6], q7 = v2[7], q8 = v2[8];
        const float p0 = q0.x, p1 = q0.y, p2 = q1.x;
        const float s00 = q1.y, s01 = q2.x;
        const float s10 = q2.y, s11 = q3.x;
        const float s20 = q3.y, s21 = q4.x;
        const float exX = q4.y, eyX = q5.x, ezX = q5.y;
        const float exY = q6.x, eyY = q6.y, ezY = q7.x;
        const float exZ = q7.y, eyZ = q8.x, ezZ = q8.y;

        const float x = t[4], y = t[5], z = t[6];

        // w = MX * (MY * (MZ * P)), P=(x,y,z,1)
        float ax = x - ezZ * y + eyZ * z + s20;
        float ay = ezZ * x + y - exZ * z + s21;
        float az = -eyZ * x + exZ * y + z + p2;
        float bx = ax - ezY * ay + eyY * az + s10;
        float by = ezY * ax + ay - exY * az + p1;
        float bz = -eyY * ax + exY * ay + az + s11;
        float cx = bx - ezX * by + eyX * bz + p0;
        float cy = ezX * bx + by - exX * bz + s00;
        float cz = -eyX * bx + exX * by + bz + s01;

        const float m1 = cx - x;
        const float m2 = cy - y;
        const float m3 = cz - z;
        const float err = sqrtf(m1 * m1 + m2 * m2 + m3 * m3 + 1e-12f);

        const float d0 = err - t[0];
        const float d1 = m1 - t[1];
        const float d2 = m2 - t[2];
        const float d3 = m3 - t[3];
        acc += d0 * d0 + d1 * d1 + d2 * d2 + d3 * d3;

        __syncthreads();            // all readers done before slot reuse

        if (tid == 0) {
            int nxt_it = it + NSTAGE - 1;
            int nxt_tile = bid + nxt_it * NBLK;
            if (nxt_tile < T) issue_tile(nxt_tile, nxt_it % NSTAGE);
        }
    }

    // ---- block reduction (deterministic) ----
    #pragma unroll
    for (int off = 16; off > 0; off >>= 1)
        acc += __shfl_down_sync(0xFFFFFFFFu, acc, off);

    __shared__ float s_warp[TPB / 32];
    const int lane = tid & 31;
    const int wid  = tid >> 5;
    if (lane == 0) s_warp[wid] = acc;
    __syncthreads();
    if (wid == 0) {
        float a = (lane < TPB / 32) ? s_warp[lane] : 0.0f;   // 4 warps
        #pragma unroll
        for (int off = 2; off > 0; off >>= 1)
            a += __shfl_down_sync(0xFFFFFFFFu, a, off);
        if (lane == 0) g_partials[bid] = a;
    }

    // ---- last-block-done final reduce ----
    __shared__ bool s_last;
    __threadfence();
    if (tid == 0) {
        unsigned int tk = atomicAdd(&g_ticket, 1u);
        s_last = (tk == gridDim.x - 1);
    }
    __syncthreads();
    if (!s_last) return;

    double sum = 0.0;
    for (int i = tid; i < (int)gridDim.x; i += TPB)
        sum += (double)__ldcg(&g_partials[i]);

    if (tid == 0) {   // remainder rows (none for 512*1024; safety)
        for (int r = T * ROWS_TILE; r < n_rows; ++r) {
            const float* v = in + (size_t)r * 18;
            const float* t = tgt + (size_t)r * 7;
            float x = t[4], y = t[5], z = t[6];
            float ax = x - v[17]*y + v[16]*z + v[7];
            float ay = v[17]*x + y - v[15]*z + v[8];
            float az = -v[16]*x + v[15]*y + z + v[2];
            float bx = ax - v[14]*ay + v[13]*az + v[5];
            float by = v[14]*ax + ay - v[12]*az + v[1];
            float bz = -v[13]*ax + v[12]*ay + az + v[6];
            float cx = bx - v[11]*by + v[10]*bz + v[0];
            float cy = v[11]*bx + by - v[9]*bz + v[3];
            float cz = -v[10]*bx + v[9]*by + bz + v[4];
            float m1 = cx - x, m2 = cy - y, m3 = cz - z;
            float err = sqrtf(m1*m1 + m2*m2 + m3*m3 + 1e-12f);
            float d0 = err - t[0], d1 = m1 - t[1], d2 = m2 - t[2], d3 = m3 - t[3];
            sum += (double)(d0*d0 + d1*d1 + d2*d2 + d3*d3);
        }
    }

    __shared__ double s_fin[TPB];
    s_fin[tid] = sum;
    __syncthreads();
    #pragma unroll
    for (int off = TPB / 2; off > 0; off >>= 1) {
        if (tid < off) s_fin[tid] += s_fin[tid + off];
        __syncthreads();
    }
    if (tid == 0) {
        out[0] = (float)(s_fin[0] / ((double)n_rows * 4.0));
        g_ticket = 0;   // reset for next graph replay
    }
}

extern "C" void kernel_launch(void* const* d_in, const int* in_sizes, int n_in,
                              void* d_out, int out_size)
{
    const float* inputs  = (const float*)d_in[0];
    const float* targets = (const float*)d_in[1];
    float* out = (float*)d_out;

    const int n_rows = in_sizes[0] / 18;                       // 524288
    const int smem_bytes = NSTAGE * TILE_BYTES + NSTAGE * 8;   // 51232

    static bool attr_set = false;
    if (!attr_set) {
        cudaFuncSetAttribute(motion_loss_tma4,
                             cudaFuncAttributeMaxDynamicSharedMemorySize,
                             smem_bytes);
        attr_set = true;
    }

    motion_loss_tma4<<<NBLK, TPB, smem_bytes>>>(inputs, targets, out, n_rows);
}